// round 3
// baseline (speedup 1.0000x reference)
#include <cuda_runtime.h>
#include <cuda_bf16.h>

// Problem: MultinomialCELoss
//   x: [N=8, Q=441, H=128, W=128] f32, y: [N=8, 2, H=128, W=128] f32
//   out[w] = -sum_{n,h} log( x[n, idx(n,h,w), h, w] )
//   idx = clip(floor((y0+110)/10),0,20)*21 + clip(floor((y1+110)/10),0,20)
//
// R3: (1) one gather per thread, grid = 1024 CTAs (max resident parallelism,
//     occ ~43%); (2) NO contended atomics — blocks write coalesced partials to
//     a device scratch [1024][128]; a second 1-CTA kernel reduces columns and
//     writes out (which also removes the zero-init launch).

#define N_  8
#define Q_  441
#define H_  128
#define W_  128
#define NBINS 21
#define ROWS_ (N_ * H_)   // 1024 partial rows

__device__ float g_scratch[ROWS_ * W_];   // 512 KB device scratch

__device__ __forceinline__ int ab_bin(float v) {
    // Match JAX f32 semantics: floor((v + 110) / 10), clipped to [0,20].
    // __fdiv_rn keeps IEEE division even under fast-math (bin boundaries).
    float q = floorf(__fdiv_rn(v + 110.0f, 10.0f));
    int qi = (int)q;
    qi = qi < 0 ? 0 : qi;
    qi = qi > (NBINS - 1) ? (NBINS - 1) : qi;
    return qi;
}

__global__ __launch_bounds__(W_) void mce_gather_kernel(
    const float* __restrict__ x,
    const float* __restrict__ y,
    float* __restrict__ scratch)
{
    const int w = threadIdx.x;   // 0..127
    const int h = blockIdx.x;    // 0..127
    const int n = blockIdx.y;    // 0..7
    const int hw = h * W_ + w;

    float ya = y[((size_t)n * 2 + 0) * (H_ * W_) + hw];
    float yb = y[((size_t)n * 2 + 1) * (H_ * W_) + hw];
    const int idx = ab_bin(ya) * NBINS + ab_bin(yb);

    float v = x[((size_t)n * Q_ + idx) * (H_ * W_) + hw];

    // Coalesced 512B row write per block; no atomics anywhere.
    scratch[(n * H_ + h) * W_ + w] = logf(v);
}

// One CTA: 8 warps-of-rows x 128 w lanes. Thread (w, r) sums rows
// r, r+8, ..., r+1016 (each iteration reads a fully-coalesced 512B row),
// then smem-reduces the 8 partials per w and writes -sum to out.
__global__ __launch_bounds__(1024) void mce_reduce_kernel(
    const float* __restrict__ scratch,
    float* __restrict__ out)
{
    const int w = threadIdx.x;   // 0..127
    const int r = threadIdx.y;   // 0..7

    // 4 accumulators -> 4 independent load/add chains (MLP).
    float a0 = 0.f, a1 = 0.f, a2 = 0.f, a3 = 0.f;
    #pragma unroll 8
    for (int k = 0; k < ROWS_ / 8; k += 4) {
        a0 += scratch[(r + 8 * (k + 0)) * W_ + w];
        a1 += scratch[(r + 8 * (k + 1)) * W_ + w];
        a2 += scratch[(r + 8 * (k + 2)) * W_ + w];
        a3 += scratch[(r + 8 * (k + 3)) * W_ + w];
    }
    float acc = (a0 + a1) + (a2 + a3);

    __shared__ float red[8][W_];
    red[r][w] = acc;
    __syncthreads();

    if (r == 0) {
        float s = 0.f;
        #pragma unroll
        for (int i = 0; i < 8; i++) s += red[i][w];
        out[w] = -s;
    }
}

extern "C" void kernel_launch(void* const* d_in, const int* in_sizes, int n_in,
                              void* d_out, int out_size) {
    const float* x = (const float*)d_in[0];
    const float* y = (const float*)d_in[1];
    float* out = (float*)d_out;

    float* scratch = nullptr;
    cudaGetSymbolAddress((void**)&scratch, g_scratch);

    dim3 grid(H_, N_);
    mce_gather_kernel<<<grid, W_>>>(x, y, scratch);
    mce_reduce_kernel<<<1, dim3(W_, 8)>>>(scratch, out);
}

// round 4
// speedup vs baseline: 1.0029x; 1.0029x over previous
#include <cuda_runtime.h>
#include <cuda_bf16.h>

// Problem: MultinomialCELoss
//   x: [N=8, Q=441, H=128, W=128] f32, y: [N=8, 2, H=128, W=128] f32
//   out[w] = -sum_{n,h} log( x[n, idx(n,h,w), h, w] )
//   idx = clip(floor((y0+110)/10),0,20)*21 + clip(floor((y1+110)/10),0,20)
//
// R4: 1024-CTA gather (proven ~1.9us in R3) + REDG atomics into SLICE-PADDED
// accumulators. R2's atomic stall was 128 contiguous f32 (512B) collapsing
// onto ~2 L2 slices (hash bits {8,10-27}, bit7 transparent). Padding each
// accumulator to 256B spreads the 128 addresses over ~64 slices:
// 1024 REDGs/address * 0.854 cyc ~ 0.5us, parallel across slices.

#define N_  8
#define Q_  441
#define H_  128
#define W_  128
#define NBINS 21
#define PAD 64                        // 64 f32 = 256B stride per accumulator

__device__ float g_acc[W_ * PAD];     // 32 KB padded accumulators

__device__ __forceinline__ int ab_bin(float v) {
    // Match JAX f32 semantics: floor((v + 110) / 10), clipped to [0,20].
    // __fdiv_rn keeps IEEE division even under fast-math (bin boundaries).
    float q = floorf(__fdiv_rn(v + 110.0f, 10.0f));
    int qi = (int)q;
    qi = qi < 0 ? 0 : qi;
    qi = qi > (NBINS - 1) ? (NBINS - 1) : qi;
    return qi;
}

__global__ __launch_bounds__(1024) void mce_zero_kernel(float* __restrict__ acc) {
    acc[blockIdx.x * 1024 + threadIdx.x] = 0.0f;
}

__global__ __launch_bounds__(W_) void mce_gather_kernel(
    const float* __restrict__ x,
    const float* __restrict__ y,
    float* __restrict__ acc)
{
    const int w = threadIdx.x;   // 0..127
    const int h = blockIdx.x;    // 0..127
    const int n = blockIdx.y;    // 0..7
    const int hw = h * W_ + w;

    float ya = y[((size_t)n * 2 + 0) * (H_ * W_) + hw];
    float yb = y[((size_t)n * 2 + 1) * (H_ * W_) + hw];
    const int idx = ab_bin(ya) * NBINS + ab_bin(yb);

    float v = x[((size_t)n * Q_ + idx) * (H_ * W_) + hw];

    // Return value unused -> REDG (fire-and-forget reduction), no round trip.
    atomicAdd(&acc[w * PAD], logf(v));
}

__global__ __launch_bounds__(W_) void mce_copy_kernel(
    const float* __restrict__ acc,
    float* __restrict__ out)
{
    const int w = threadIdx.x;
    out[w] = -acc[w * PAD];
}

extern "C" void kernel_launch(void* const* d_in, const int* in_sizes, int n_in,
                              void* d_out, int out_size) {
    const float* x = (const float*)d_in[0];
    const float* y = (const float*)d_in[1];
    float* out = (float*)d_out;

    float* acc = nullptr;
    cudaGetSymbolAddress((void**)&acc, g_acc);

    mce_zero_kernel<<<(W_ * PAD) / 1024, 1024>>>(acc);
    dim3 grid(H_, N_);
    mce_gather_kernel<<<grid, W_>>>(x, y, acc);
    mce_copy_kernel<<<1, W_>>>(acc, out);
}

// round 5
// speedup vs baseline: 1.0269x; 1.0239x over previous
#include <cuda_runtime.h>
#include <cuda_bf16.h>

// Problem: MultinomialCELoss
//   x: [N=8, Q=441, H=128, W=128] f32, y: [N=8, 2, H=128, W=128] f32
//   out[w] = -sum_{n,h} log( x[n, idx(n,h,w), h, w] )
//
// R5: launch-count is the bottleneck (R4: a trivial zero kernel profiled at
// 3.0us => ~2-3us per graph node). Fuse zero/gather/reduce/writeback into ONE
// kernel: REDG atomics into 256B-padded accumulators (R4 slice spreading),
// then threadfence + arrival counter; the last CTA writes out[] and resets
// the device globals to their zero-initialized state for graph replay.

#define N_  8
#define Q_  441
#define H_  128
#define W_  128
#define HW_ (H_ * W_)
#define NBINS 21
#define PAD 64                       // 256B stride per accumulator
#define GRID 256
#define TPB 512
#define ROWS_PER_CTA 4               // 1024 (n,h) rows / 256 CTAs

__device__ float g_acc[W_ * PAD];    // zero-initialized at module load
__device__ unsigned int g_count;     // zero-initialized at module load

__device__ __forceinline__ int ab_bin(float v) {
    // Match JAX f32 semantics: floor((v + 110) / 10), clipped to [0,20].
    // __fdiv_rn keeps IEEE division even under fast-math (bin boundaries).
    float q = floorf(__fdiv_rn(v + 110.0f, 10.0f));
    int qi = (int)q;
    qi = qi < 0 ? 0 : qi;
    qi = qi > (NBINS - 1) ? (NBINS - 1) : qi;
    return qi;
}

__global__ __launch_bounds__(TPB) void mce_fused_kernel(
    const float* __restrict__ x,
    const float* __restrict__ y,
    float* __restrict__ out)
{
    const int tid = threadIdx.x;
    const int w = tid & (W_ - 1);            // 0..127
    const int r = tid >> 7;                  // 0..3
    const int row = blockIdx.x * ROWS_PER_CTA + r;   // 0..1023
    const int n = row >> 7;                  // 0..7
    const int h = row & (H_ - 1);            // 0..127
    const int hw = h * W_ + w;

    float ya = y[(size_t)(n * 2 + 0) * HW_ + hw];
    float yb = y[(size_t)(n * 2 + 1) * HW_ + hw];
    const int idx = ab_bin(ya) * NBINS + ab_bin(yb);

    float v = x[((size_t)n * Q_ + idx) * HW_ + hw];

    // Fire-and-forget reduction (REDG). Padded stride spreads the 128
    // accumulator addresses across L2 slices (hash bits {8,10-27}).
    atomicAdd(&g_acc[w * PAD], logf(v));

    // Make this CTA's REDGs globally visible before signaling arrival.
    __threadfence();
    __syncthreads();

    __shared__ unsigned int s_last;
    if (tid == 0) {
        s_last = (atomicAdd(&g_count, 1u) == GRID - 1) ? 1u : 0u;
    }
    __syncthreads();

    if (s_last) {
        __threadfence();  // acquire: order accumulator reads after counter obs
        if (tid < W_) {
            float s = g_acc[tid * PAD];
            out[tid] = -s;
            g_acc[tid * PAD] = 0.0f;   // restore zero state for next replay
        }
        if (tid == 0) g_count = 0u;    // restore counter for next replay
    }
}

extern "C" void kernel_launch(void* const* d_in, const int* in_sizes, int n_in,
                              void* d_out, int out_size) {
    const float* x = (const float*)d_in[0];
    const float* y = (const float*)d_in[1];
    float* out = (float*)d_out;

    mce_fused_kernel<<<GRID, TPB>>>(x, y, out);
}